// round 3
// baseline (speedup 1.0000x reference)
#include <cuda_runtime.h>
#include <cuda_bf16.h>

// DecayModel: out[b,s,h] = (fwd[s] + bwd[s]) / norm[s] per (b,h) column.
// fwd[s] = sum_{k<=s} 0.5^{s-k} x[k];  bwd[s] = sum_{k>=s} 0.5^{k-s} x[k];
// norm[s] = 4 - 2^-s - 2^-(S-1-s)  (== 4.0f exactly in fp32 for 22<=s<=S-23).
//
// Chunked with decay halo: each thread owns one (b,h) column and a CHUNK=32
// span of S, warming up over a HALO=20 halo on each side (truncation < 2^-20).
// Warp spans 32 consecutive h -> all accesses are single 128B lines.
// Forward scan register-resident; backward pass reconstructs
// x[t] = fwd[t] - 0.5*fwd[t-1] so x is read exactly once per owning thread.
// Neighbor chunks' halo reads hit L2 (wave-concurrent blocks share lines).

#define S_DIM 2048
#define H_DIM 1024
#define CHUNK 32
#define HALO  20
#define NCH   (S_DIM / CHUNK)   // 64
#define TPB   256

__global__ __launch_bounds__(TPB, 3)
void decay_model_kernel(const float* __restrict__ x, float* __restrict__ out) {
    const int h  = blockIdx.x * TPB + threadIdx.x;   // h column (coalesced)
    const int ci = blockIdx.y;                       // chunk index along S
    const int s0 = ci * CHUNK;
    const size_t base = (size_t)blockIdx.z * S_DIM * H_DIM + h;
    const float* __restrict__ xc = x + base;
    float* __restrict__ oc = out + base;

    // ---- Left-halo warmup (zero contribution before s=0) ----
    float y = 0.0f;
    if (ci != 0) {
        #pragma unroll
        for (int t = 0; t < HALO; ++t)
            y = fmaf(y, 0.5f, xc[(size_t)(s0 - HALO + t) * H_DIM]);
    }
    const float y_left = y;

    // ---- Forward scan, register resident ----
    float fwd[CHUNK];
    #pragma unroll
    for (int t = 0; t < CHUNK; ++t) {
        y = fmaf(y, 0.5f, xc[(size_t)(s0 + t) * H_DIM]);
        fwd[t] = y;
    }

    // ---- Right-halo warmup ----
    float z = 0.0f;
    if (ci != NCH - 1) {
        #pragma unroll
        for (int t = HALO - 1; t >= 0; --t)
            z = fmaf(z, 0.5f, xc[(size_t)(s0 + CHUNK + t) * H_DIM]);
    }

    // ---- Backward scan + combine + normalize + streaming store ----
    if (ci == 0 || ci == NCH - 1) {
        // Boundary chunks: exact norm via exp2f (2 of 64 chunks).
        #pragma unroll
        for (int t = CHUNK - 1; t >= 0; --t) {
            float prev = (t > 0) ? fwd[t - 1] : y_left;
            float xv = fmaf(-0.5f, prev, fwd[t]);
            z = fmaf(z, 0.5f, xv);
            int s = s0 + t;
            float norm = 4.0f - exp2f(-(float)s) - exp2f(-(float)(S_DIM - 1 - s));
            __stcs(&oc[(size_t)s * H_DIM], (fwd[t] + z) / norm);
        }
    } else {
        // Interior: norm == 4.0f exactly in fp32.
        #pragma unroll
        for (int t = CHUNK - 1; t >= 0; --t) {
            float prev = (t > 0) ? fwd[t - 1] : y_left;
            float xv = fmaf(-0.5f, prev, fwd[t]);
            z = fmaf(z, 0.5f, xv);
            __stcs(&oc[(size_t)(s0 + t) * H_DIM], (fwd[t] + z) * 0.25f);
        }
    }
}

extern "C" void kernel_launch(void* const* d_in, const int* in_sizes, int n_in,
                              void* d_out, int out_size) {
    const float* x = (const float*)d_in[0];
    float* out = (float*)d_out;
    const int B = in_sizes[0] / (S_DIM * H_DIM);

    dim3 grid(H_DIM / TPB, NCH, B);   // (4, 64, B) = 4096 blocks of 256 threads
    decay_model_kernel<<<grid, TPB>>>(x, out);
}